// round 3
// baseline (speedup 1.0000x reference)
#include <cuda_runtime.h>
#include <math.h>

#define Bb 2
#define Dd 192
#define Hh 56
#define Ww 56
#define Nn 16
#define Rr 12
#define Kk 4
#define LL (Hh*Ww)      /* 3136 */
#define TP 64           /* positions per prep tile */
#define CH 44           /* R + 2N */
#define PF 16           /* scan prefetch pad */
#define XSTR 204        /* xs smem row stride (words): 12p mod 32 distinct per 8-lane phase */

// ---------------- device scratch (static, no runtime alloc) ----------------
// All per-direction arrays stored in TRAVERSAL order -> scan is purely affine.
__device__ float2 g_dz[2*Bb*Kk*LL*Dd + PF*Dd];   // (softplus(delta), delta*u)
__device__ float2 g_BC[2*Bb*Kk*LL*16 + PF*16];   // per (row,no): {B0,B1},{C0,C1}
__device__ float  g_yk[2*Bb*Kk*LL*Dd];           // per-direction scan outputs (traversal idx)
__device__ float  g_xT[2*Bb*LL*Dd];              // x transposed to [pos][d] (canonical)

__device__ __forceinline__ float ex2(float x) {
    float r; asm("ex2.approx.ftz.f32 %0, %1;" : "=f"(r) : "f"(x)); return r;
}
__device__ __forceinline__ float lg2(float x) {
    float r; asm("lg2.approx.ftz.f32 %0, %1;" : "=f"(r) : "f"(x)); return r;
}
#define LOG2E 1.44269504088896340736f
#define LN2   0.69314718055994530942f

__device__ __forceinline__ int tau_of(int k, int pos) {
    int t1 = (pos % Ww) * Hh + pos / Ww;
    switch (k) {
        case 0: return pos;
        case 1: return t1;
        case 2: return LL - 1 - pos;
        default: return LL - 1 - t1;
    }
}

// ---------------- kernel 1: projections + precompute ----------------
// grid (L/TP, B, 2), 256 threads. Register-blocked GEMM: 4 pos x 3 ch per thread.
__global__ void __launch_bounds__(256, 2)
prep_kernel(const float* __restrict__ x1, const float* __restrict__ x2,
            const float* __restrict__ pw1, const float* __restrict__ pw2,
            const float* __restrict__ dtw1, const float* __restrict__ dtw2,
            const float* __restrict__ dtb1, const float* __restrict__ dtb2)
{
    extern __shared__ float sm[];
    float* xs   = sm;                    // [TP][XSTR]
    float* Ws   = xs + TP*XSTR;          // [44][192]
    float* dtws = Ws + CH*Dd;            // [192][13]
    float* bsm  = dtws + Dd*13;          // [192]
    float* dblS = bsm + Dd;              // [44][66]

    const int t    = threadIdx.x;
    const int pos0 = blockIdx.x * TP;
    const int b    = blockIdx.y;
    const int s    = blockIdx.z;
    const float* x   = s ? x2   : x1;
    const float* pw  = s ? pw2  : pw1;
    const float* dtw = s ? dtw2 : dtw1;
    const float* dtb = s ? dtb2 : dtb1;
    const int sb  = s*2 + b;
    const int sbo = (s^1)*2 + b;

    // load x tile transposed into smem: xs[p][d]
    for (int e = t; e < Dd*TP; e += 256) {
        int d = e / TP, p = e % TP;
        xs[p*XSTR + d] = x[(b*Dd + d)*LL + pos0 + p];
    }
    __syncthreads();
    // canonical-order transposed x for the merge kernel
    for (int e = t; e < TP*Dd; e += 256) {
        int p = e / Dd, d = e - p*Dd;
        g_xT[(size_t)(sb*LL + pos0 + p)*Dd + d] = xs[p*XSTR + d];
    }

    const int pg = t & 15;               // position group (4 pos)
    const int cb = t >> 4;               // 0..15 channel base
    const int wrow2 = (cb < 12) ? (cb + 32) : cb;   // safe addr; result discarded if cb>=12

    for (int k = 0; k < Kk; k++) {
        for (int e = t; e < CH*Dd; e += 256) Ws[e] = pw[k*CH*Dd + e];
        for (int e = t; e < Dd*Rr; e += 256) { int d = e/Rr, r = e%Rr; dtws[d*13+r] = dtw[k*Dd*Rr + e]; }
        if (t < Dd) bsm[t] = dtb[k*Dd + t];
        __syncthreads();

        // ---- GEMM: dbl[c][p] = sum_d W[c][d] * x[d][p], 4 pos x 3 ch per thread ----
        {
            float acc[4][3];
            #pragma unroll
            for (int i = 0; i < 4; i++)
                #pragma unroll
                for (int j = 0; j < 3; j++) acc[i][j] = 0.f;

            #pragma unroll 4
            for (int d4 = 0; d4 < Dd; d4 += 4) {
                float4 wv0 = *(const float4*)&Ws[ cb       *Dd + d4];
                float4 wv1 = *(const float4*)&Ws[(cb + 16 )*Dd + d4];
                float4 wv2 = *(const float4*)&Ws[ wrow2    *Dd + d4];
                #pragma unroll
                for (int i = 0; i < 4; i++) {
                    float4 xv = *(const float4*)&xs[(pg*4 + i)*XSTR + d4];
                    acc[i][0] = fmaf(wv0.x, xv.x, acc[i][0]);
                    acc[i][0] = fmaf(wv0.y, xv.y, acc[i][0]);
                    acc[i][0] = fmaf(wv0.z, xv.z, acc[i][0]);
                    acc[i][0] = fmaf(wv0.w, xv.w, acc[i][0]);
                    acc[i][1] = fmaf(wv1.x, xv.x, acc[i][1]);
                    acc[i][1] = fmaf(wv1.y, xv.y, acc[i][1]);
                    acc[i][1] = fmaf(wv1.z, xv.z, acc[i][1]);
                    acc[i][1] = fmaf(wv1.w, xv.w, acc[i][1]);
                    acc[i][2] = fmaf(wv2.x, xv.x, acc[i][2]);
                    acc[i][2] = fmaf(wv2.y, xv.y, acc[i][2]);
                    acc[i][2] = fmaf(wv2.z, xv.z, acc[i][2]);
                    acc[i][2] = fmaf(wv2.w, xv.w, acc[i][2]);
                }
            }
            #pragma unroll
            for (int i = 0; i < 4; i++) {
                dblS[ cb      *66 + pg*4 + i] = acc[i][0];
                dblS[(cb+16)  *66 + pg*4 + i] = acc[i][1];
                if (cb < 12) dblS[(cb+32)*66 + pg*4 + i] = acc[i][2];
            }
        }
        __syncthreads();

        // ---- store packed B(own)/C(cross), traversal order, n-paired (no, no+8) ----
        for (int e = t; e < TP*8; e += 256) {
            int p = e >> 3, no = e & 7;
            int tauv = tau_of(k, pos0 + p);
            float2 bv = make_float2(dblS[(12+no)*66+p], dblS[(20+no)*66+p]);
            float2 cv = make_float2(dblS[(28+no)*66+p], dblS[(36+no)*66+p]);
            g_BC[((size_t)(sb *Kk + k)*LL + tauv)*16 + no*2    ] = bv;
            g_BC[((size_t)(sbo*Kk + k)*LL + tauv)*16 + no*2 + 1] = cv;
        }

        // ---- dt = dtw @ dbl[0:12] + bias, softplus, z = dt*u ; traversal-order store ----
        for (int e = t; e < TP*Dd; e += 256) {
            int p = e / Dd, d = e - p*Dd;
            float a = bsm[d];
            #pragma unroll
            for (int r = 0; r < 12; r++) a = fmaf(dtws[d*13+r], dblS[r*66 + p], a);
            float em = ex2(-fabsf(a) * LOG2E);
            float sp = fmaxf(a, 0.f) + lg2(1.f + em) * LN2;
            float z  = sp * xs[p*XSTR + d];
            int tauv = tau_of(k, pos0 + p);
            g_dz[((size_t)(sb*Kk + k)*LL + tauv)*Dd + d] = make_float2(sp, z);
        }
        __syncthreads();
    }
}

// ---------------- kernel 2: selective scan (phase-split, ping-pong prefetch) ----------------
// grid (48, K, S*B), 32 threads. lane = dl*8 + no; thread owns states (no, no+8) of d.
__global__ void __launch_bounds__(32) scan_kernel(const float* __restrict__ A1,
                                                  const float* __restrict__ A2)
{
    const int lane = threadIdx.x;
    const int dl = lane >> 3, no = lane & 7;
    const int k  = blockIdx.y;
    const int sb = blockIdx.z;
    const int s  = sb >> 1;
    const int d  = blockIdx.x*4 + dl;

    const float* Alog = s ? A2 : A1;
    const float a0 = -__expf(Alog[(k*Dd + d)*Nn + no    ]) * LOG2E;
    const float a1 = -__expf(Alog[(k*Dd + d)*Nn + no + 8]) * LOG2E;

    const int row0 = (sb*Kk + k)*LL;
    const float2* dzp = g_dz + (size_t)row0*Dd + d;
    const float4* bcp = (const float4*)g_BC + (size_t)row0*8 + no;
    float*        yp  = g_yk + (size_t)row0*Dd + d;

    float2 dzb[2][8];
    float4 bcb[2][8];
    #pragma unroll
    for (int j = 0; j < 8; j++) {
        dzb[0][j] = dzp[j*Dd];       bcb[0][j] = bcp[j*8];
        dzb[1][j] = dzp[(8+j)*Dd];   bcb[1][j] = bcp[(8+j)*8];
    }

    float h0 = 0.f, h1 = 0.f;
    int tt = 0;
    for (int it = 0; it < LL/16; it++) {
        #pragma unroll
        for (int ss = 0; ss < 2; ss++) {
            float e0[8], e1[8], fb0[8], fb1[8], y[8];
            // phase 1: independent exps + input products
            #pragma unroll
            for (int j = 0; j < 8; j++) {
                e0[j]  = ex2(dzb[ss][j].x * a0);
                e1[j]  = ex2(dzb[ss][j].x * a1);
                fb0[j] = dzb[ss][j].y * bcb[ss][j].x;
                fb1[j] = dzb[ss][j].y * bcb[ss][j].y;
            }
            // phase 2: recurrence (4-cyc chain) + y partials
            #pragma unroll
            for (int j = 0; j < 8; j++) {
                h0 = fmaf(e0[j], h0, fb0[j]);
                h1 = fmaf(e1[j], h1, fb1[j]);
                y[j] = fmaf(h1, bcb[ss][j].w, h0 * bcb[ss][j].z);
            }
            // phase 3: prefetch batch tt+16 into this slot (used 2 bodies later)
            #pragma unroll
            for (int j = 0; j < 8; j++) {
                dzb[ss][j] = dzp[(tt + 16 + j)*Dd];
                bcb[ss][j] = bcp[(tt + 16 + j)*8];
            }
            // phase 4: 8 independent shfl trees, pipelined per level
            #pragma unroll
            for (int j = 0; j < 8; j++) y[j] += __shfl_xor_sync(0xffffffffu, y[j], 1);
            #pragma unroll
            for (int j = 0; j < 8; j++) y[j] += __shfl_xor_sync(0xffffffffu, y[j], 2);
            #pragma unroll
            for (int j = 0; j < 8; j++) y[j] += __shfl_xor_sync(0xffffffffu, y[j], 4);
            if (no == 0) {
                #pragma unroll
                for (int j = 0; j < 8; j++) yp[(tt + j)*Dd] = y[j];
            }
            tt += 8;
        }
    }
}

// ---------------- kernel 3: merge (sum k) + D*u + LayerNorm ----------------
__global__ void merge_ln_kernel(const float* __restrict__ D1s, const float* __restrict__ D2s,
                                const float* __restrict__ lnw, const float* __restrict__ lnb,
                                float* __restrict__ out)
{
    __shared__ float red[6];
    const int rid = blockIdx.x;
    const int sb = rid / LL, pos = rid % LL;
    const int s = sb >> 1;
    const int d = threadIdx.x;
    const float* Ds = s ? D2s : D1s;

    const int t1 = (pos % Ww) * Hh + pos / Ww;
    const int base = sb*Kk*LL;
    float v = g_yk[(size_t)(base          + pos       )*Dd + d]
            + g_yk[(size_t)(base + 1*LL   + t1        )*Dd + d]
            + g_yk[(size_t)(base + 2*LL   + (LL-1-pos))*Dd + d]
            + g_yk[(size_t)(base + 3*LL   + (LL-1-t1) )*Dd + d];
    const float Dsum = Ds[d] + Ds[Dd + d] + Ds[2*Dd + d] + Ds[3*Dd + d];
    v = fmaf(Dsum, g_xT[(size_t)(sb*LL + pos)*Dd + d], v);

    float tsum = v;
    #pragma unroll
    for (int o = 16; o; o >>= 1) tsum += __shfl_xor_sync(0xffffffffu, tsum, o);
    if ((d & 31) == 0) red[d >> 5] = tsum;
    __syncthreads();
    const float mu = (red[0]+red[1]+red[2]+red[3]+red[4]+red[5]) * (1.f/192.f);
    const float dv = v - mu;
    __syncthreads();
    float q = dv*dv;
    #pragma unroll
    for (int o = 16; o; o >>= 1) q += __shfl_xor_sync(0xffffffffu, q, o);
    if ((d & 31) == 0) red[d >> 5] = q;
    __syncthreads();
    const float var = (red[0]+red[1]+red[2]+red[3]+red[4]+red[5]) * (1.f/192.f);

    out[rid*Dd + d] = dv * rsqrtf(var + 1e-5f) * lnw[d] + lnb[d];
}

// ---------------- launch ----------------
extern "C" void kernel_launch(void* const* d_in, const int* in_sizes, int n_in,
                              void* d_out, int out_size)
{
    const float* x1   = (const float*)d_in[0];
    const float* x2   = (const float*)d_in[1];
    const float* pw1  = (const float*)d_in[2];
    const float* pw2  = (const float*)d_in[3];
    const float* dtw1 = (const float*)d_in[4];
    const float* dtw2 = (const float*)d_in[5];
    const float* dtb1 = (const float*)d_in[6];
    const float* dtb2 = (const float*)d_in[7];
    const float* A1   = (const float*)d_in[8];
    const float* A2   = (const float*)d_in[9];
    const float* D1s  = (const float*)d_in[10];
    const float* D2s  = (const float*)d_in[11];
    const float* lnw  = (const float*)d_in[12];
    const float* lnb  = (const float*)d_in[13];
    float* out = (float*)d_out;

    const int smem = (TP*XSTR + CH*Dd + Dd*13 + Dd + CH*66) * (int)sizeof(float); // 108384 B
    cudaFuncSetAttribute(prep_kernel, cudaFuncAttributeMaxDynamicSharedMemorySize, smem);

    prep_kernel<<<dim3(LL/TP, Bb, 2), 256, smem>>>(x1, x2, pw1, pw2, dtw1, dtw2, dtb1, dtb2);
    scan_kernel<<<dim3(Dd/4, Kk, 2*Bb), 32>>>(A1, A2);
    merge_ln_kernel<<<2*Bb*LL, Dd>>>(D1s, D2s, lnw, lnb, out);
}

// round 4
// speedup vs baseline: 1.2565x; 1.2565x over previous
#include <cuda_runtime.h>
#include <math.h>

#define Bb 2
#define Dd 192
#define Hh 56
#define Ww 56
#define Nn 16
#define Rr 12
#define Kk 4
#define LL (Hh*Ww)      /* 3136 */
#define TP 64           /* positions per prep tile */
#define CH 44           /* R + 2N */
#define CHP 48          /* padded channels */
#define PF 64           /* scan prefetch pad (>= 48 steps) */
#define XSTR 196        /* xs smem row stride (words); lane-stride-1 in p -> conflict-free */
#define DSTR 66         /* dblS row stride */
#define ST 16           /* scan steps per tile */
#define NT (LL/ST)      /* 196 tiles */

// ---------------- device scratch (static, no runtime alloc) ----------------
__device__ float2 g_dz[2*Bb*Kk*LL*Dd + PF*Dd];   // (softplus(delta), delta*u), traversal order
__device__ float2 g_BC[2*Bb*Kk*LL*16 + PF*16];   // per (row,no): {B0,B1},{C0,C1}, traversal order
__device__ float  g_yk[2*Bb*Kk*LL*Dd];           // per-direction scan outputs (traversal idx)
__device__ float  g_xT[2*Bb*LL*Dd];              // x transposed to [pos][d] (canonical)

__device__ __forceinline__ float ex2(float x) {
    float r; asm("ex2.approx.ftz.f32 %0, %1;" : "=f"(r) : "f"(x)); return r;
}
__device__ __forceinline__ float lg2(float x) {
    float r; asm("lg2.approx.ftz.f32 %0, %1;" : "=f"(r) : "f"(x)); return r;
}
#define LOG2E 1.44269504088896340736f
#define LN2   0.69314718055994530942f

__device__ __forceinline__ int tau_of(int k, int pos) {
    int t1 = (pos % Ww) * Hh + pos / Ww;
    switch (k) {
        case 0: return pos;
        case 1: return t1;
        case 2: return LL - 1 - pos;
        default: return LL - 1 - t1;
    }
}

// ---------------- kernel 1: projections + precompute ----------------
// grid (L/TP, B, 2), 256 threads. Thread = (pg, cb): 4 pos {pg+16i} x 3 ch {cb,cb+16,cb+32}.
__global__ void __launch_bounds__(256, 2)
prep_kernel(const float* __restrict__ x1, const float* __restrict__ x2,
            const float* __restrict__ pw1, const float* __restrict__ pw2,
            const float* __restrict__ dtw1, const float* __restrict__ dtw2,
            const float* __restrict__ dtb1, const float* __restrict__ dtb2)
{
    extern __shared__ float sm[];
    float* xs   = sm;                    // [TP][XSTR]
    float* Ws   = xs + TP*XSTR;          // [48][192] (rows 44..47 zero)
    float* dtws = Ws + CHP*Dd;           // [192][20]
    float* bsm  = dtws + Dd*20;          // [192]
    float* dblS = bsm + Dd;              // [48][DSTR]

    const int t    = threadIdx.x;
    const int pos0 = blockIdx.x * TP;
    const int b    = blockIdx.y;
    const int s    = blockIdx.z;
    const float* x   = s ? x2   : x1;
    const float* pw  = s ? pw2  : pw1;
    const float* dtw = s ? dtw2 : dtw1;
    const float* dtb = s ? dtb2 : dtb1;
    const int sb  = s*2 + b;
    const int sbo = (s^1)*2 + b;

    // load x tile transposed into smem: xs[p][d]
    for (int e = t; e < Dd*TP; e += 256) {
        int d = e / TP, p = e % TP;
        xs[p*XSTR + d] = x[(b*Dd + d)*LL + pos0 + p];
    }
    __syncthreads();
    // canonical-order transposed x for merge
    for (int e = t; e < TP*Dd; e += 256) {
        int p = e / Dd, d = e - p*Dd;
        g_xT[(size_t)(sb*LL + pos0 + p)*Dd + d] = xs[p*XSTR + d];
    }

    const int pg = t & 15;
    const int cb = t >> 4;

    for (int k = 0; k < Kk; k++) {
        for (int e = t; e < CHP*Dd; e += 256) Ws[e] = (e < CH*Dd) ? pw[k*CH*Dd + e] : 0.f;
        for (int e = t; e < Dd*Rr; e += 256) { int d = e/Rr, r = e - d*Rr; dtws[d*20+r] = dtw[k*Dd*Rr + e]; }
        if (t < Dd) bsm[t] = dtb[k*Dd + t];
        __syncthreads();

        // ---- GEMM: dbl[c][p] = sum_d W[c][d] * x[d][p]; 4 pos x 3 ch per thread ----
        {
            float acc[4][3];
            #pragma unroll
            for (int i = 0; i < 4; i++)
                #pragma unroll
                for (int j = 0; j < 3; j++) acc[i][j] = 0.f;

            #pragma unroll 2
            for (int d4 = 0; d4 < Dd; d4 += 4) {
                float4 w0 = *(const float4*)&Ws[ cb      *Dd + d4];
                float4 w1 = *(const float4*)&Ws[(cb+16) *Dd + d4];
                float4 w2 = *(const float4*)&Ws[(cb+32) *Dd + d4];
                #pragma unroll
                for (int i = 0; i < 4; i++) {
                    float4 xv = *(const float4*)&xs[(pg + 16*i)*XSTR + d4];
                    acc[i][0] = fmaf(w0.x, xv.x, acc[i][0]);
                    acc[i][0] = fmaf(w0.y, xv.y, acc[i][0]);
                    acc[i][0] = fmaf(w0.z, xv.z, acc[i][0]);
                    acc[i][0] = fmaf(w0.w, xv.w, acc[i][0]);
                    acc[i][1] = fmaf(w1.x, xv.x, acc[i][1]);
                    acc[i][1] = fmaf(w1.y, xv.y, acc[i][1]);
                    acc[i][1] = fmaf(w1.z, xv.z, acc[i][1]);
                    acc[i][1] = fmaf(w1.w, xv.w, acc[i][1]);
                    acc[i][2] = fmaf(w2.x, xv.x, acc[i][2]);
                    acc[i][2] = fmaf(w2.y, xv.y, acc[i][2]);
                    acc[i][2] = fmaf(w2.z, xv.z, acc[i][2]);
                    acc[i][2] = fmaf(w2.w, xv.w, acc[i][2]);
                }
            }
            #pragma unroll
            for (int i = 0; i < 4; i++) {
                dblS[ cb     *DSTR + pg + 16*i] = acc[i][0];
                dblS[(cb+16) *DSTR + pg + 16*i] = acc[i][1];
                dblS[(cb+32) *DSTR + pg + 16*i] = acc[i][2];
            }
        }
        __syncthreads();

        // ---- store packed B(own)/C(cross), traversal order, n-paired (no, no+8) ----
        for (int e = t; e < TP*8; e += 256) {
            int p = e >> 3, no = e & 7;
            int tauv = tau_of(k, pos0 + p);
            float2 bv = make_float2(dblS[(12+no)*DSTR+p], dblS[(20+no)*DSTR+p]);
            float2 cv = make_float2(dblS[(28+no)*DSTR+p], dblS[(36+no)*DSTR+p]);
            g_BC[((size_t)(sb *Kk + k)*LL + tauv)*16 + no*2    ] = bv;
            g_BC[((size_t)(sbo*Kk + k)*LL + tauv)*16 + no*2 + 1] = cv;
        }

        // ---- dt = dtw @ dbl[0:12] + bias, softplus, z = dt*u ; traversal-order store ----
        for (int e = t; e < TP*Dd; e += 256) {
            int p = e / Dd, d = e - p*Dd;
            float4 wa = *(const float4*)&dtws[d*20 + 0];
            float4 wb = *(const float4*)&dtws[d*20 + 4];
            float4 wc = *(const float4*)&dtws[d*20 + 8];
            float a = bsm[d];
            a = fmaf(wa.x, dblS[0*DSTR+p],  a); a = fmaf(wa.y, dblS[1*DSTR+p],  a);
            a = fmaf(wa.z, dblS[2*DSTR+p],  a); a = fmaf(wa.w, dblS[3*DSTR+p],  a);
            a = fmaf(wb.x, dblS[4*DSTR+p],  a); a = fmaf(wb.y, dblS[5*DSTR+p],  a);
            a = fmaf(wb.z, dblS[6*DSTR+p],  a); a = fmaf(wb.w, dblS[7*DSTR+p],  a);
            a = fmaf(wc.x, dblS[8*DSTR+p],  a); a = fmaf(wc.y, dblS[9*DSTR+p],  a);
            a = fmaf(wc.z, dblS[10*DSTR+p], a); a = fmaf(wc.w, dblS[11*DSTR+p], a);
            float em = ex2(-fabsf(a) * LOG2E);
            float sp = fmaxf(a, 0.f) + lg2(1.f + em) * LN2;
            float z  = sp * xs[p*XSTR + d];
            int tauv = tau_of(k, pos0 + p);
            g_dz[((size_t)(sb*Kk + k)*LL + tauv)*Dd + d] = make_float2(sp, z);
        }
        __syncthreads();
    }
}

// ---------------- kernel 2: selective scan (cp.async 3-stage smem pipeline) ----------------
// grid (48, K, S*B), 32 threads. lane = dl*8 + no; thread owns states (no, no+8) of d.
__global__ void __launch_bounds__(32) scan_kernel(const float* __restrict__ A1,
                                                  const float* __restrict__ A2)
{
    __shared__ float2 s_dz[3][ST*4];    // 1.5 KB
    __shared__ float4 s_bc[3][ST*8];    // 6 KB

    const int lane = threadIdx.x;
    const int dl = lane >> 3, no = lane & 7;
    const int k  = blockIdx.y;
    const int sb = blockIdx.z;
    const int s  = sb >> 1;
    const int d  = blockIdx.x*4 + dl;

    const float* Alog = s ? A2 : A1;
    const float a0 = -__expf(Alog[(k*Dd + d)*Nn + no    ]) * LOG2E;
    const float a1 = -__expf(Alog[(k*Dd + d)*Nn + no + 8]) * LOG2E;

    const int row0 = (sb*Kk + k)*LL;
    const int d0   = blockIdx.x*4;
    // per-lane cp.async source bases
    const float2* dz_src0 = g_dz + ((size_t)row0 + (lane>>1))*Dd + d0 + (lane&1)*2;  // 16B = 2 float2
    const float4* bc_src0 = (const float4*)g_BC + (size_t)row0*8 + lane;
    float* yp = g_yk + (size_t)row0*Dd + d;

    #define LOAD_TILE(slot, tile) do {                                                   \
        unsigned za = (unsigned)__cvta_generic_to_shared(&s_dz[slot][2*lane]);           \
        asm volatile("cp.async.cg.shared.global [%0], [%1], 16;" ::                      \
                     "r"(za), "l"(dz_src0 + (size_t)(tile)*ST*Dd));                      \
        _Pragma("unroll")                                                                \
        for (int q = 0; q < 4; q++) {                                                    \
            unsigned ba = (unsigned)__cvta_generic_to_shared(&s_bc[slot][q*32 + lane]);  \
            asm volatile("cp.async.cg.shared.global [%0], [%1], 16;" ::                  \
                         "r"(ba), "l"(bc_src0 + (size_t)(tile)*ST*8 + q*32));            \
        }                                                                                \
        asm volatile("cp.async.commit_group;");                                          \
    } while (0)

    LOAD_TILE(0, 0);
    LOAD_TILE(1, 1);
    LOAD_TILE(2, 2);

    float h0 = 0.f, h1 = 0.f;
    for (int it = 0; it < NT; it++) {
        const int slot = it % 3;
        const int tt = it * ST;
        asm volatile("cp.async.wait_group 2;");
        __syncwarp();

        #pragma unroll
        for (int hb = 0; hb < 2; hb++) {
            float2 dzr[8]; float4 bcr[8];
            #pragma unroll
            for (int j = 0; j < 8; j++) {
                dzr[j] = s_dz[slot][(hb*8 + j)*4 + dl];
                bcr[j] = s_bc[slot][(hb*8 + j)*8 + no];
            }
            float e0[8], e1[8], y[8];
            #pragma unroll
            for (int j = 0; j < 8; j++) {
                e0[j] = ex2(dzr[j].x * a0);
                e1[j] = ex2(dzr[j].x * a1);
            }
            #pragma unroll
            for (int j = 0; j < 8; j++) {
                h0 = fmaf(e0[j], h0, dzr[j].y * bcr[j].x);
                h1 = fmaf(e1[j], h1, dzr[j].y * bcr[j].y);
                y[j] = fmaf(h1, bcr[j].w, h0 * bcr[j].z);
            }
            #pragma unroll
            for (int j = 0; j < 8; j++) y[j] += __shfl_xor_sync(0xffffffffu, y[j], 1);
            #pragma unroll
            for (int j = 0; j < 8; j++) y[j] += __shfl_xor_sync(0xffffffffu, y[j], 2);
            #pragma unroll
            for (int j = 0; j < 8; j++) y[j] += __shfl_xor_sync(0xffffffffu, y[j], 4);
            if (no == 0) {
                #pragma unroll
                for (int j = 0; j < 8; j++) yp[(tt + hb*8 + j)*Dd] = y[j];
            }
        }
        __syncwarp();
        LOAD_TILE(slot, it + 3);     // pad region covers tiles NT..NT+2
    }
    asm volatile("cp.async.wait_group 0;");
}

// ---------------- kernel 3: merge (sum k) + D*u + LayerNorm ----------------
__global__ void merge_ln_kernel(const float* __restrict__ D1s, const float* __restrict__ D2s,
                                const float* __restrict__ lnw, const float* __restrict__ lnb,
                                float* __restrict__ out)
{
    __shared__ float red[6];
    const int rid = blockIdx.x;
    const int sb = rid / LL, pos = rid % LL;
    const int s = sb >> 1;
    const int d = threadIdx.x;
    const float* Ds = s ? D2s : D1s;

    const int t1 = (pos % Ww) * Hh + pos / Ww;
    const int base = sb*Kk*LL;
    float v = g_yk[(size_t)(base          + pos       )*Dd + d]
            + g_yk[(size_t)(base + 1*LL   + t1        )*Dd + d]
            + g_yk[(size_t)(base + 2*LL   + (LL-1-pos))*Dd + d]
            + g_yk[(size_t)(base + 3*LL   + (LL-1-t1) )*Dd + d];
    const float Dsum = Ds[d] + Ds[Dd + d] + Ds[2*Dd + d] + Ds[3*Dd + d];
    v = fmaf(Dsum, g_xT[(size_t)(sb*LL + pos)*Dd + d], v);

    float tsum = v;
    #pragma unroll
    for (int o = 16; o; o >>= 1) tsum += __shfl_xor_sync(0xffffffffu, tsum, o);
    if ((d & 31) == 0) red[d >> 5] = tsum;
    __syncthreads();
    const float mu = (red[0]+red[1]+red[2]+red[3]+red[4]+red[5]) * (1.f/192.f);
    const float dv = v - mu;
    __syncthreads();
    float q = dv*dv;
    #pragma unroll
    for (int o = 16; o; o >>= 1) q += __shfl_xor_sync(0xffffffffu, q, o);
    if ((d & 31) == 0) red[d >> 5] = q;
    __syncthreads();
    const float var = (red[0]+red[1]+red[2]+red[3]+red[4]+red[5]) * (1.f/192.f);

    out[rid*Dd + d] = dv * rsqrtf(var + 1e-5f) * lnw[d] + lnb[d];
}

// ---------------- launch ----------------
extern "C" void kernel_launch(void* const* d_in, const int* in_sizes, int n_in,
                              void* d_out, int out_size)
{
    const float* x1   = (const float*)d_in[0];
    const float* x2   = (const float*)d_in[1];
    const float* pw1  = (const float*)d_in[2];
    const float* pw2  = (const float*)d_in[3];
    const float* dtw1 = (const float*)d_in[4];
    const float* dtw2 = (const float*)d_in[5];
    const float* dtb1 = (const float*)d_in[6];
    const float* dtb2 = (const float*)d_in[7];
    const float* A1   = (const float*)d_in[8];
    const float* A2   = (const float*)d_in[9];
    const float* D1s  = (const float*)d_in[10];
    const float* D2s  = (const float*)d_in[11];
    const float* lnw  = (const float*)d_in[12];
    const float* lnb  = (const float*)d_in[13];
    float* out = (float*)d_out;

    const int smem = (TP*XSTR + CHP*Dd + Dd*20 + Dd + CHP*DSTR) * (int)sizeof(float); // 115840 B
    cudaFuncSetAttribute(prep_kernel, cudaFuncAttributeMaxDynamicSharedMemorySize, smem);

    prep_kernel<<<dim3(LL/TP, Bb, 2), 256, smem>>>(x1, x2, pw1, pw2, dtw1, dtw2, dtb1, dtb2);
    scan_kernel<<<dim3(Dd/4, Kk, 2*Bb), 32>>>(A1, A2);
    merge_ln_kernel<<<2*Bb*LL, Dd>>>(D1s, D2s, lnw, lnb, out);
}

// round 5
// speedup vs baseline: 1.4197x; 1.1299x over previous
#include <cuda_runtime.h>
#include <math.h>

#define Bb 2
#define Dd 192
#define Hh 56
#define Ww 56
#define Nn 16
#define Rr 12
#define Kk 4
#define LL (Hh*Ww)      /* 3136 */
#define TP 64           /* positions per prep tile */
#define CH 44           /* R + 2N */
#define CHP 48          /* padded channels */
#define PF 64           /* scan prefetch pad rows (>= 48) */
#define XSTR 196        /* xs smem row stride (words) */
#define DSTR 66         /* dblS row stride */
#define ST 16           /* scan steps per tile */
#define NT (LL/ST)      /* 196 tiles */

// ---------------- device scratch (static, no runtime alloc) ----------------
__device__ float2 g_dz[2*Bb*Kk*LL*Dd + PF*Dd];   // (softplus(delta), delta*u), traversal order
__device__ float2 g_BC[2*Bb*Kk*LL*16 + PF*16];   // per (row,no): {B0,B1},{C0,C1}, traversal order
__device__ float  g_yk[2*Bb*Kk*LL*Dd];           // per-direction scan outputs (traversal idx)
__device__ float  g_xT[2*Bb*LL*Dd];              // x transposed to [pos][d] (canonical)

__device__ __forceinline__ float ex2(float x) {
    float r; asm("ex2.approx.ftz.f32 %0, %1;" : "=f"(r) : "f"(x)); return r;
}
__device__ __forceinline__ float lg2(float x) {
    float r; asm("lg2.approx.ftz.f32 %0, %1;" : "=f"(r) : "f"(x)); return r;
}
#define LOG2E 1.44269504088896340736f
#define LN2   0.69314718055994530942f

__device__ __forceinline__ int tau_of(int k, int pos) {
    int t1 = (pos % Ww) * Hh + pos / Ww;
    switch (k) {
        case 0: return pos;
        case 1: return t1;
        case 2: return LL - 1 - pos;
        default: return LL - 1 - t1;
    }
}

// ---------------- kernel 1: projections + precompute ----------------
// grid (49, K, SB), 256 threads, one k per block. Thread = (pg, cb): 4 pos x 3 ch.
__global__ void __launch_bounds__(256, 2)
prep_kernel(const float* __restrict__ x1, const float* __restrict__ x2,
            const float* __restrict__ pw1, const float* __restrict__ pw2,
            const float* __restrict__ dtw1, const float* __restrict__ dtw2,
            const float* __restrict__ dtb1, const float* __restrict__ dtb2)
{
    extern __shared__ float sm[];
    float* xs   = sm;                    // [TP][XSTR]
    float* Ws   = xs + TP*XSTR;          // [48][192] (rows 44..47 zero)
    float* dtws = Ws + CHP*Dd;           // [192][12] packed, stride-12 conflict-free
    float* bsm  = dtws + Dd*12;          // [192]
    float* dblS = bsm + Dd;              // [48][DSTR]

    const int t    = threadIdx.x;
    const int pos0 = blockIdx.x * TP;
    const int k    = blockIdx.y;
    const int sbz  = blockIdx.z;
    const int s    = sbz >> 1, b = sbz & 1;
    const float* x   = s ? x2   : x1;
    const float* pw  = s ? pw2  : pw1;
    const float* dtw = s ? dtw2 : dtw1;
    const float* dtb = s ? dtb2 : dtb1;
    const int sb  = s*2 + b;
    const int sbo = (s^1)*2 + b;

    // load x tile transposed into smem: xs[p][d]; also stage weights
    for (int e = t; e < Dd*TP; e += 256) {
        int d = e / TP, p = e % TP;
        xs[p*XSTR + d] = x[(b*Dd + d)*LL + pos0 + p];
    }
    for (int e = t; e < CHP*Dd; e += 256) Ws[e] = (e < CH*Dd) ? pw[k*CH*Dd + e] : 0.f;
    for (int e = t; e < Dd*Rr; e += 256) dtws[e] = dtw[k*Dd*Rr + e];   // [d][r] packed
    if (t < Dd) bsm[t] = dtb[k*Dd + t];
    __syncthreads();

    // canonical-order transposed x for merge (write once, k==0 blocks only)
    if (k == 0) {
        for (int e = t; e < TP*Dd; e += 256) {
            int p = e / Dd, d = e - p*Dd;
            g_xT[(size_t)(sb*LL + pos0 + p)*Dd + d] = xs[p*XSTR + d];
        }
    }

    const int pg = t & 15;
    const int cb = t >> 4;

    // ---- GEMM: dbl[c][p] = sum_d W[c][d] * x[d][p]; 4 pos x 3 ch per thread ----
    {
        float acc[4][3];
        #pragma unroll
        for (int i = 0; i < 4; i++)
            #pragma unroll
            for (int j = 0; j < 3; j++) acc[i][j] = 0.f;

        #pragma unroll 2
        for (int d4 = 0; d4 < Dd; d4 += 4) {
            float4 w0 = *(const float4*)&Ws[ cb      *Dd + d4];
            float4 w1 = *(const float4*)&Ws[(cb+16) *Dd + d4];
            float4 w2 = *(const float4*)&Ws[(cb+32) *Dd + d4];
            #pragma unroll
            for (int i = 0; i < 4; i++) {
                float4 xv = *(const float4*)&xs[(pg + 16*i)*XSTR + d4];
                acc[i][0] = fmaf(w0.x, xv.x, acc[i][0]);
                acc[i][0] = fmaf(w0.y, xv.y, acc[i][0]);
                acc[i][0] = fmaf(w0.z, xv.z, acc[i][0]);
                acc[i][0] = fmaf(w0.w, xv.w, acc[i][0]);
                acc[i][1] = fmaf(w1.x, xv.x, acc[i][1]);
                acc[i][1] = fmaf(w1.y, xv.y, acc[i][1]);
                acc[i][1] = fmaf(w1.z, xv.z, acc[i][1]);
                acc[i][1] = fmaf(w1.w, xv.w, acc[i][1]);
                acc[i][2] = fmaf(w2.x, xv.x, acc[i][2]);
                acc[i][2] = fmaf(w2.y, xv.y, acc[i][2]);
                acc[i][2] = fmaf(w2.z, xv.z, acc[i][2]);
                acc[i][2] = fmaf(w2.w, xv.w, acc[i][2]);
            }
        }
        #pragma unroll
        for (int i = 0; i < 4; i++) {
            dblS[ cb     *DSTR + pg + 16*i] = acc[i][0];
            dblS[(cb+16) *DSTR + pg + 16*i] = acc[i][1];
            dblS[(cb+32) *DSTR + pg + 16*i] = acc[i][2];
        }
    }
    __syncthreads();

    // ---- store packed B(own)/C(cross), traversal order, n-paired (no, no+8) ----
    for (int e = t; e < TP*8; e += 256) {
        int p = e >> 3, no = e & 7;
        int tauv = tau_of(k, pos0 + p);
        float2 bv = make_float2(dblS[(12+no)*DSTR+p], dblS[(20+no)*DSTR+p]);
        float2 cv = make_float2(dblS[(28+no)*DSTR+p], dblS[(36+no)*DSTR+p]);
        g_BC[((size_t)(sb *Kk + k)*LL + tauv)*16 + no*2    ] = bv;
        g_BC[((size_t)(sbo*Kk + k)*LL + tauv)*16 + no*2 + 1] = cv;
    }

    // ---- dt = dtw @ dbl[0:12] + bias, softplus, z = dt*u ; traversal-order store ----
    for (int e = t; e < TP*Dd; e += 256) {
        int p = e / Dd, d = e - p*Dd;
        const float4* dw = (const float4*)&dtws[d*12];
        float4 wa = dw[0], wb = dw[1], wc = dw[2];
        float a = bsm[d];
        a = fmaf(wa.x, dblS[0*DSTR+p],  a); a = fmaf(wa.y, dblS[1*DSTR+p],  a);
        a = fmaf(wa.z, dblS[2*DSTR+p],  a); a = fmaf(wa.w, dblS[3*DSTR+p],  a);
        a = fmaf(wb.x, dblS[4*DSTR+p],  a); a = fmaf(wb.y, dblS[5*DSTR+p],  a);
        a = fmaf(wb.z, dblS[6*DSTR+p],  a); a = fmaf(wb.w, dblS[7*DSTR+p],  a);
        a = fmaf(wc.x, dblS[8*DSTR+p],  a); a = fmaf(wc.y, dblS[9*DSTR+p],  a);
        a = fmaf(wc.z, dblS[10*DSTR+p], a); a = fmaf(wc.w, dblS[11*DSTR+p], a);
        float em = ex2(-fabsf(a) * LOG2E);
        float sp = fmaxf(a, 0.f) + lg2(1.f + em) * LN2;
        float z  = sp * xs[p*XSTR + d];
        int tauv = tau_of(k, pos0 + p);
        g_dz[((size_t)(sb*Kk + k)*LL + tauv)*Dd + d] = make_float2(sp, z);
    }
}

// ---------------- kernel 2: selective scan ----------------
// grid (12, K, SB), 128 threads (4 warps -> all 4 SMSPs). Warp w owns d-chunk
// d0 = bx*16 + w*4; lane = dl*8+no owns states (no, no+8) of d0+dl.
// BC tile shared across the block (loaded by warp 0), dz tiles per-warp.
__global__ void __launch_bounds__(128) scan_kernel(const float* __restrict__ A1,
                                                   const float* __restrict__ A2)
{
    __shared__ float2 s_dz[4][3][ST*4];   // per-warp dz tiles, 6 KB
    __shared__ float4 s_bc[3][ST*8];      // shared BC tiles, 6 KB

    const int tid  = threadIdx.x;
    const int w    = tid >> 5;
    const int lane = tid & 31;
    const int dl = lane >> 3, no = lane & 7;
    const int k  = blockIdx.y;
    const int sb = blockIdx.z;
    const int s  = sb >> 1;
    const int d0 = blockIdx.x*16 + w*4;
    const int d  = d0 + dl;

    const float* Alog = s ? A2 : A1;
    const float a0 = -__expf(Alog[(k*Dd + d)*Nn + no    ]) * LOG2E;
    const float a1 = -__expf(Alog[(k*Dd + d)*Nn + no + 8]) * LOG2E;

    const int row0 = (sb*Kk + k)*LL;
    // cp.async sources: dz per warp (16B per lane), bc shared (4x16B per warp-0 lane)
    const float4* dz_src0 = (const float4*)g_dz + (size_t)row0*(Dd/4)
                          + (lane>>1)*(Dd/4) + (d0>>2)*2/2;   // see note below
    // (Dd floats per row = Dd/2 float2 = Dd/4... compute cleanly:)
    const float4* dz_base = (const float4*)g_dz;               // 2 float2 per float4
    const size_t  dz_row_f4 = Dd/2;                            // float4 per row (192 float2 -> 96)
    const float4* dz_src = dz_base + ((size_t)row0 + (lane>>1))*dz_row_f4 + (d0>>1) + (lane&1);
    const float4* bc_src = (const float4*)g_BC + (size_t)row0*8 + lane;
    float* yp = g_yk + (size_t)row0*Dd + d;

    #define LOAD_TILE(slot, tile) do {                                                   \
        unsigned za = (unsigned)__cvta_generic_to_shared(&s_dz[w][slot][2*lane]);        \
        asm volatile("cp.async.cg.shared.global [%0], [%1], 16;" ::                      \
                     "r"(za), "l"(dz_src + (size_t)(tile)*ST*dz_row_f4));                \
        if (w == 0) {                                                                    \
            _Pragma("unroll")                                                            \
            for (int q = 0; q < 4; q++) {                                                \
                unsigned ba = (unsigned)__cvta_generic_to_shared(&s_bc[slot][q*32+lane]);\
                asm volatile("cp.async.cg.shared.global [%0], [%1], 16;" ::              \
                             "r"(ba), "l"(bc_src + (size_t)(tile)*ST*8 + q*32));         \
            }                                                                            \
        }                                                                                \
        asm volatile("cp.async.commit_group;");                                          \
    } while (0)

    LOAD_TILE(0, 0);
    LOAD_TILE(1, 1);
    LOAD_TILE(2, 2);

    float h0 = 0.f, h1 = 0.f;
    for (int it = 0; it < NT; it++) {
        const int slot = it % 3;
        const int tt = it * ST;
        asm volatile("cp.async.wait_group 2;");
        __syncthreads();

        float yy[16];
        #pragma unroll
        for (int hb = 0; hb < 2; hb++) {
            float2 dzr[8]; float4 bcr[8];
            #pragma unroll
            for (int j = 0; j < 8; j++) {
                dzr[j] = s_dz[w][slot][(hb*8 + j)*4 + dl];
                bcr[j] = s_bc[slot][(hb*8 + j)*8 + no];
            }
            float e0[8], e1[8];
            #pragma unroll
            for (int j = 0; j < 8; j++) {
                e0[j] = ex2(dzr[j].x * a0);
                e1[j] = ex2(dzr[j].x * a1);
            }
            #pragma unroll
            for (int j = 0; j < 8; j++) {
                h0 = fmaf(e0[j], h0, dzr[j].y * bcr[j].x);
                h1 = fmaf(e1[j], h1, dzr[j].y * bcr[j].y);
                yy[hb*8 + j] = fmaf(h1, bcr[j].w, h0 * bcr[j].z);
            }
        }
        // 16 independent shfl reduction trees (pipelined)
        #pragma unroll
        for (int j = 0; j < 16; j++) yy[j] += __shfl_xor_sync(0xffffffffu, yy[j], 1);
        #pragma unroll
        for (int j = 0; j < 16; j++) yy[j] += __shfl_xor_sync(0xffffffffu, yy[j], 2);
        #pragma unroll
        for (int j = 0; j < 16; j++) yy[j] += __shfl_xor_sync(0xffffffffu, yy[j], 4);
        if (no == 0) {
            #pragma unroll
            for (int j = 0; j < 16; j++) yp[(tt + j)*Dd] = yy[j];
        }
        __syncthreads();
        LOAD_TILE(slot, it + 3);     // pad region covers tiles NT..NT+2
    }
    asm volatile("cp.async.wait_group 0;");
    #undef LOAD_TILE
}

// ---------------- kernel 3: merge (sum k) + D*u + LayerNorm ----------------
__global__ void merge_ln_kernel(const float* __restrict__ D1s, const float* __restrict__ D2s,
                                const float* __restrict__ lnw, const float* __restrict__ lnb,
                                float* __restrict__ out)
{
    __shared__ float red[6];
    const int rid = blockIdx.x;
    const int sb = rid / LL, pos = rid % LL;
    const int s = sb >> 1;
    const int d = threadIdx.x;
    const float* Ds = s ? D2s : D1s;

    const int t1 = (pos % Ww) * Hh + pos / Ww;
    const int base = sb*Kk*LL;
    float v = g_yk[(size_t)(base          + pos       )*Dd + d]
            + g_yk[(size_t)(base + 1*LL   + t1        )*Dd + d]
            + g_yk[(size_t)(base + 2*LL   + (LL-1-pos))*Dd + d]
            + g_yk[(size_t)(base + 3*LL   + (LL-1-t1) )*Dd + d];
    const float Dsum = Ds[d] + Ds[Dd + d] + Ds[2*Dd + d] + Ds[3*Dd + d];
    v = fmaf(Dsum, g_xT[(size_t)(sb*LL + pos)*Dd + d], v);

    float tsum = v;
    #pragma unroll
    for (int o = 16; o; o >>= 1) tsum += __shfl_xor_sync(0xffffffffu, tsum, o);
    if ((d & 31) == 0) red[d >> 5] = tsum;
    __syncthreads();
    const float mu = (red[0]+red[1]+red[2]+red[3]+red[4]+red[5]) * (1.f/192.f);
    const float dv = v - mu;
    __syncthreads();
    float q = dv*dv;
    #pragma unroll
    for (int o = 16; o; o >>= 1) q += __shfl_xor_sync(0xffffffffu, q, o);
    if ((d & 31) == 0) red[d >> 5] = q;
    __syncthreads();
    const float var = (red[0]+red[1]+red[2]+red[3]+red[4]+red[5]) * (1.f/192.f);

    out[rid*Dd + d] = dv * rsqrtf(var + 1e-5f) * lnw[d] + lnb[d];
}

// ---------------- launch ----------------
extern "C" void kernel_launch(void* const* d_in, const int* in_sizes, int n_in,
                              void* d_out, int out_size)
{
    const float* x1   = (const float*)d_in[0];
    const float* x2   = (const float*)d_in[1];
    const float* pw1  = (const float*)d_in[2];
    const float* pw2  = (const float*)d_in[3];
    const float* dtw1 = (const float*)d_in[4];
    const float* dtw2 = (const float*)d_in[5];
    const float* dtb1 = (const float*)d_in[6];
    const float* dtb2 = (const float*)d_in[7];
    const float* A1   = (const float*)d_in[8];
    const float* A2   = (const float*)d_in[9];
    const float* D1s  = (const float*)d_in[10];
    const float* D2s  = (const float*)d_in[11];
    const float* lnw  = (const float*)d_in[12];
    const float* lnb  = (const float*)d_in[13];
    float* out = (float*)d_out;

    const int smem = (TP*XSTR + CHP*Dd + Dd*12 + Dd + CHP*DSTR) * (int)sizeof(float); // 109,696 B
    cudaFuncSetAttribute(prep_kernel, cudaFuncAttributeMaxDynamicSharedMemorySize, smem);

    prep_kernel<<<dim3(LL/TP, Kk, 4), 256, smem>>>(x1, x2, pw1, pw2, dtw1, dtw2, dtb1, dtb2);
    scan_kernel<<<dim3(Dd/16, Kk, 2*Bb), 128>>>(A1, A2);
    merge_ln_kernel<<<2*Bb*LL, Dd>>>(D1s, D2s, lnw, lnb, out);
}

// round 6
// speedup vs baseline: 1.5198x; 1.0705x over previous
#include <cuda_runtime.h>
#include <math.h>

#define Bb 2
#define Dd 192
#define Hh 56
#define Ww 56
#define Nn 16
#define Rr 12
#define Kk 4
#define LL (Hh*Ww)      /* 3136 */
#define TP 64           /* positions per prep tile */
#define CH 44           /* R + 2N */
#define CHP 48          /* padded channels */
#define PF 64           /* scan prefetch pad rows (>= 64 steps) */
#define XSTR 196        /* xs smem row stride (words) */
#define DSTR 66         /* dblS row stride */
#define ST 16           /* scan steps per tile */
#define NT (LL/ST)      /* 196 tiles */

typedef unsigned long long u64;

// ---------------- device scratch (static, no runtime alloc) ----------------
__device__ float2 g_dz[2*Bb*Kk*LL*Dd + PF*Dd];   // (softplus(delta), delta*u), traversal order
__device__ float2 g_BC[2*Bb*Kk*LL*16 + PF*16];   // per (row,no): {B0,B1},{C0,C1}, traversal order
__device__ float  g_yk[2*Bb*Kk*LL*Dd];           // per-direction scan outputs (traversal idx)
__device__ float  g_xT[2*Bb*LL*Dd];              // x transposed to [pos][d] (canonical)

__device__ __forceinline__ float ex2(float x) {
    float r; asm("ex2.approx.ftz.f32 %0, %1;" : "=f"(r) : "f"(x)); return r;
}
__device__ __forceinline__ float lg2(float x) {
    float r; asm("lg2.approx.ftz.f32 %0, %1;" : "=f"(r) : "f"(x)); return r;
}
__device__ __forceinline__ u64 ffma2(u64 a, u64 b, u64 c) {
    u64 r; asm("fma.rn.f32x2 %0, %1, %2, %3;" : "=l"(r) : "l"(a), "l"(b), "l"(c)); return r;
}
__device__ __forceinline__ float hadd2(u64 v) {
    float lo, hi; asm("mov.b64 {%0, %1}, %2;" : "=f"(lo), "=f"(hi) : "l"(v)); return lo + hi;
}
#define LOG2E 1.44269504088896340736f
#define LN2   0.69314718055994530942f

__device__ __forceinline__ int tau_of(int k, int pos) {
    int t1 = (pos % Ww) * Hh + pos / Ww;
    switch (k) {
        case 0: return pos;
        case 1: return t1;
        case 2: return LL - 1 - pos;
        default: return LL - 1 - t1;
    }
}

// ---------------- kernel 1: projections + precompute ----------------
// grid (49, K, SB), 256 threads, one k per block. Thread = (pg, cb): 4 pos x 3 ch.
// GEMM inner product uses packed fma.rn.f32x2 over the K (=d) reduction dim.
__global__ void __launch_bounds__(256, 2)
prep_kernel(const float* __restrict__ x1, const float* __restrict__ x2,
            const float* __restrict__ pw1, const float* __restrict__ pw2,
            const float* __restrict__ dtw1, const float* __restrict__ dtw2,
            const float* __restrict__ dtb1, const float* __restrict__ dtb2)
{
    extern __shared__ float sm[];
    float* xs   = sm;                    // [TP][XSTR]
    float* Ws   = xs + TP*XSTR;          // [48][192] (rows 44..47 zero)
    float* dtws = Ws + CHP*Dd;           // [192][12] packed
    float* bsm  = dtws + Dd*12;          // [192]
    float* dblS = bsm + Dd;              // [48][DSTR]

    const int t    = threadIdx.x;
    const int pos0 = blockIdx.x * TP;
    const int k    = blockIdx.y;
    const int sbz  = blockIdx.z;
    const int s    = sbz >> 1, b = sbz & 1;
    const float* x   = s ? x2   : x1;
    const float* pw  = s ? pw2  : pw1;
    const float* dtw = s ? dtw2 : dtw1;
    const float* dtb = s ? dtb2 : dtb1;
    const int sb  = s*2 + b;
    const int sbo = (s^1)*2 + b;

    for (int e = t; e < Dd*TP; e += 256) {
        int d = e / TP, p = e % TP;
        xs[p*XSTR + d] = x[(b*Dd + d)*LL + pos0 + p];
    }
    for (int e = t; e < CHP*Dd; e += 256) Ws[e] = (e < CH*Dd) ? pw[k*CH*Dd + e] : 0.f;
    for (int e = t; e < Dd*Rr; e += 256) dtws[e] = dtw[k*Dd*Rr + e];
    if (t < Dd) bsm[t] = dtb[k*Dd + t];
    __syncthreads();

    if (k == 0) {
        for (int e = t; e < TP*Dd; e += 256) {
            int p = e / Dd, d = e - p*Dd;
            g_xT[(size_t)(sb*LL + pos0 + p)*Dd + d] = xs[p*XSTR + d];
        }
    }

    const int pg = t & 15;
    const int cb = t >> 4;

    // ---- GEMM: dbl[c][p] = sum_d W[c][d] * x[d][p]; 4 pos x 3 ch, f32x2 packed K ----
    {
        u64 acc2[4][3];
        #pragma unroll
        for (int i = 0; i < 4; i++)
            #pragma unroll
            for (int j = 0; j < 3; j++) acc2[i][j] = 0ull;

        #pragma unroll 2
        for (int d4 = 0; d4 < Dd; d4 += 4) {
            ulonglong2 w0 = *(const ulonglong2*)&Ws[ cb      *Dd + d4];
            ulonglong2 w1 = *(const ulonglong2*)&Ws[(cb+16) *Dd + d4];
            ulonglong2 w2 = *(const ulonglong2*)&Ws[(cb+32) *Dd + d4];
            #pragma unroll
            for (int i = 0; i < 4; i++) {
                ulonglong2 xv = *(const ulonglong2*)&xs[(pg + 16*i)*XSTR + d4];
                acc2[i][0] = ffma2(xv.x, w0.x, acc2[i][0]);
                acc2[i][0] = ffma2(xv.y, w0.y, acc2[i][0]);
                acc2[i][1] = ffma2(xv.x, w1.x, acc2[i][1]);
                acc2[i][1] = ffma2(xv.y, w1.y, acc2[i][1]);
                acc2[i][2] = ffma2(xv.x, w2.x, acc2[i][2]);
                acc2[i][2] = ffma2(xv.y, w2.y, acc2[i][2]);
            }
        }
        #pragma unroll
        for (int i = 0; i < 4; i++) {
            dblS[ cb     *DSTR + pg + 16*i] = hadd2(acc2[i][0]);
            dblS[(cb+16) *DSTR + pg + 16*i] = hadd2(acc2[i][1]);
            dblS[(cb+32) *DSTR + pg + 16*i] = hadd2(acc2[i][2]);
        }
    }
    __syncthreads();

    // ---- store packed B(own)/C(cross), traversal order, n-paired (no, no+8) ----
    for (int e = t; e < TP*8; e += 256) {
        int p = e >> 3, no = e & 7;
        int tauv = tau_of(k, pos0 + p);
        float2 bv = make_float2(dblS[(12+no)*DSTR+p], dblS[(20+no)*DSTR+p]);
        float2 cv = make_float2(dblS[(28+no)*DSTR+p], dblS[(36+no)*DSTR+p]);
        g_BC[((size_t)(sb *Kk + k)*LL + tauv)*16 + no*2    ] = bv;
        g_BC[((size_t)(sbo*Kk + k)*LL + tauv)*16 + no*2 + 1] = cv;
    }

    // ---- dt = dtw @ dbl[0:12] + bias, softplus, z = dt*u ; traversal-order store ----
    for (int e = t; e < TP*Dd; e += 256) {
        int p = e / Dd, d = e - p*Dd;
        const float4* dw = (const float4*)&dtws[d*12];
        float4 wa = dw[0], wb = dw[1], wc = dw[2];
        float a = bsm[d];
        a = fmaf(wa.x, dblS[0*DSTR+p],  a); a = fmaf(wa.y, dblS[1*DSTR+p],  a);
        a = fmaf(wa.z, dblS[2*DSTR+p],  a); a = fmaf(wa.w, dblS[3*DSTR+p],  a);
        a = fmaf(wb.x, dblS[4*DSTR+p],  a); a = fmaf(wb.y, dblS[5*DSTR+p],  a);
        a = fmaf(wb.z, dblS[6*DSTR+p],  a); a = fmaf(wb.w, dblS[7*DSTR+p],  a);
        a = fmaf(wc.x, dblS[8*DSTR+p],  a); a = fmaf(wc.y, dblS[9*DSTR+p],  a);
        a = fmaf(wc.z, dblS[10*DSTR+p], a); a = fmaf(wc.w, dblS[11*DSTR+p], a);
        float em = ex2(-fabsf(a) * LOG2E);
        float sp = fmaxf(a, 0.f) + lg2(1.f + em) * LN2;
        float z  = sp * xs[p*XSTR + d];
        int tauv = tau_of(k, pos0 + p);
        g_dz[((size_t)(sb*Kk + k)*LL + tauv)*Dd + d] = make_float2(sp, z);
    }
}

// ---------------- kernel 2: selective scan ----------------
// grid (12, K, SB), 128 threads. Warps fully INDEPENDENT (private dz+BC smem tiles,
// no block barriers). 4-stage cp.async ring, prefetch distance 3.
__global__ void __launch_bounds__(128) scan_kernel(const float* __restrict__ A1,
                                                   const float* __restrict__ A2)
{
    __shared__ float2 s_dz[4][4][ST*4];   // [warp][stage][...]  8 KB
    __shared__ float4 s_bc[4][4][ST*8];   // [warp][stage][...] 32 KB

    const int tid  = threadIdx.x;
    const int w    = tid >> 5;
    const int lane = tid & 31;
    const int dl = lane >> 3, no = lane & 7;
    const int k  = blockIdx.y;
    const int sb = blockIdx.z;
    const int s  = sb >> 1;
    const int d0 = blockIdx.x*16 + w*4;
    const int d  = d0 + dl;

    const float* Alog = s ? A2 : A1;
    const float a0 = -__expf(Alog[(k*Dd + d)*Nn + no    ]) * LOG2E;
    const float a1 = -__expf(Alog[(k*Dd + d)*Nn + no + 8]) * LOG2E;

    const int row0 = (sb*Kk + k)*LL;
    const size_t dz_row_f4 = Dd/2;     // float4 per dz row
    const float4* dz_src = (const float4*)g_dz + ((size_t)row0 + (lane>>1))*dz_row_f4
                         + (d0>>1) + (lane&1);
    const float4* bc_src = (const float4*)g_BC + (size_t)row0*8 + lane;
    float* yp = g_yk + (size_t)row0*Dd + d;

    #define LOAD_TILE(slot, tile) do {                                                   \
        unsigned za = (unsigned)__cvta_generic_to_shared(&s_dz[w][slot][2*lane]);        \
        asm volatile("cp.async.cg.shared.global [%0], [%1], 16;" ::                      \
                     "r"(za), "l"(dz_src + (size_t)(tile)*ST*dz_row_f4));                \
        _Pragma("unroll")                                                                \
        for (int q = 0; q < 4; q++) {                                                    \
            unsigned ba = (unsigned)__cvta_generic_to_shared(&s_bc[w][slot][q*32+lane]); \
            asm volatile("cp.async.cg.shared.global [%0], [%1], 16;" ::                  \
                         "r"(ba), "l"(bc_src + (size_t)(tile)*ST*8 + q*32));             \
        }                                                                                \
        asm volatile("cp.async.commit_group;");                                          \
    } while (0)

    LOAD_TILE(0, 0);
    LOAD_TILE(1, 1);
    LOAD_TILE(2, 2);

    float h0 = 0.f, h1 = 0.f;
    for (int it = 0; it < NT; it++) {
        const int slot = it & 3;
        const int tt = it * ST;
        asm volatile("cp.async.wait_group 2;");
        __syncwarp();
        LOAD_TILE((it + 3) & 3, it + 3);    // issue next tile before compute (pad covers tail)

        float yy[16];
        #pragma unroll
        for (int hb = 0; hb < 2; hb++) {
            float2 dzr[8]; float4 bcr[8];
            #pragma unroll
            for (int j = 0; j < 8; j++) {
                dzr[j] = s_dz[w][slot][(hb*8 + j)*4 + dl];
                bcr[j] = s_bc[w][slot][(hb*8 + j)*8 + no];
            }
            float e0[8], e1[8];
            #pragma unroll
            for (int j = 0; j < 8; j++) {
                e0[j] = ex2(dzr[j].x * a0);
                e1[j] = ex2(dzr[j].x * a1);
            }
            #pragma unroll
            for (int j = 0; j < 8; j++) {
                h0 = fmaf(e0[j], h0, dzr[j].y * bcr[j].x);
                h1 = fmaf(e1[j], h1, dzr[j].y * bcr[j].y);
                yy[hb*8 + j] = fmaf(h1, bcr[j].w, h0 * bcr[j].z);
            }
        }
        #pragma unroll
        for (int j = 0; j < 16; j++) yy[j] += __shfl_xor_sync(0xffffffffu, yy[j], 1);
        #pragma unroll
        for (int j = 0; j < 16; j++) yy[j] += __shfl_xor_sync(0xffffffffu, yy[j], 2);
        #pragma unroll
        for (int j = 0; j < 16; j++) yy[j] += __shfl_xor_sync(0xffffffffu, yy[j], 4);
        if (no == 0) {
            #pragma unroll
            for (int j = 0; j < 16; j++) yp[(tt + j)*Dd] = yy[j];
        }
    }
    asm volatile("cp.async.wait_group 0;");
    #undef LOAD_TILE
}

// ---------------- kernel 3: merge (sum k) + D*u + LayerNorm ----------------
__global__ void merge_ln_kernel(const float* __restrict__ D1s, const float* __restrict__ D2s,
                                const float* __restrict__ lnw, const float* __restrict__ lnb,
                                float* __restrict__ out)
{
    __shared__ float red[6];
    const int rid = blockIdx.x;
    const int sb = rid / LL, pos = rid % LL;
    const int s = sb >> 1;
    const int d = threadIdx.x;
    const float* Ds = s ? D2s : D1s;

    const int t1 = (pos % Ww) * Hh + pos / Ww;
    const int base = sb*Kk*LL;
    float v = g_yk[(size_t)(base          + pos       )*Dd + d]
            + g_yk[(size_t)(base + 1*LL   + t1        )*Dd + d]
            + g_yk[(size_t)(base + 2*LL   + (LL-1-pos))*Dd + d]
            + g_yk[(size_t)(base + 3*LL   + (LL-1-t1) )*Dd + d];
    const float Dsum = Ds[d] + Ds[Dd + d] + Ds[2*Dd + d] + Ds[3*Dd + d];
    v = fmaf(Dsum, g_xT[(size_t)(sb*LL + pos)*Dd + d], v);

    float tsum = v;
    #pragma unroll
    for (int o = 16; o; o >>= 1) tsum += __shfl_xor_sync(0xffffffffu, tsum, o);
    if ((d & 31) == 0) red[d >> 5] = tsum;
    __syncthreads();
    const float mu = (red[0]+red[1]+red[2]+red[3]+red[4]+red[5]) * (1.f/192.f);
    const float dv = v - mu;
    __syncthreads();
    float q = dv*dv;
    #pragma unroll
    for (int o = 16; o; o >>= 1) q += __shfl_xor_sync(0xffffffffu, q, o);
    if ((d & 31) == 0) red[d >> 5] = q;
    __syncthreads();
    const float var = (red[0]+red[1]+red[2]+red[3]+red[4]+red[5]) * (1.f/192.f);

    out[rid*Dd + d] = dv * rsqrtf(var + 1e-5f) * lnw[d] + lnb[d];
}

// ---------------- launch ----------------
extern "C" void kernel_launch(void* const* d_in, const int* in_sizes, int n_in,
                              void* d_out, int out_size)
{
    const float* x1   = (const float*)d_in[0];
    const float* x2   = (const float*)d_in[1];
    const float* pw1  = (const float*)d_in[2];
    const float* pw2  = (const float*)d_in[3];
    const float* dtw1 = (const float*)d_in[4];
    const float* dtw2 = (const float*)d_in[5];
    const float* dtb1 = (const float*)d_in[6];
    const float* dtb2 = (const float*)d_in[7];
    const float* A1   = (const float*)d_in[8];
    const float* A2   = (const float*)d_in[9];
    const float* D1s  = (const float*)d_in[10];
    const float* D2s  = (const float*)d_in[11];
    const float* lnw  = (const float*)d_in[12];
    const float* lnb  = (const float*)d_in[13];
    float* out = (float*)d_out;

    const int smem = (TP*XSTR + CHP*Dd + Dd*12 + Dd + CHP*DSTR) * (int)sizeof(float); // 109,696 B
    cudaFuncSetAttribute(prep_kernel, cudaFuncAttributeMaxDynamicSharedMemorySize, smem);

    prep_kernel<<<dim3(LL/TP, Kk, 4), 256, smem>>>(x1, x2, pw1, pw2, dtw1, dtw2, dtb1, dtb2);
    scan_kernel<<<dim3(Dd/16, Kk, 2*Bb), 128>>>(A1, A2);
    merge_ln_kernel<<<2*Bb*LL, Dd>>>(D1s, D2s, lnw, lnb, out);
}

// round 7
// speedup vs baseline: 1.7925x; 1.1794x over previous
#include <cuda_runtime.h>
#include <math.h>

#define Bb 2
#define Dd 192
#define Hh 56
#define Ww 56
#define Nn 16
#define Rr 12
#define Kk 4
#define LL (Hh*Ww)      /* 3136 */
#define TP 64           /* positions per prep tile */
#define CH 44           /* R + 2N */
#define CHP 48          /* padded channels */
#define PF 64           /* scan prefetch pad rows (>= 64 steps) */
#define XSTR 196        /* xs smem row stride (words) */
#define DSTR 66         /* dblS row stride */
#define ST 16           /* scan steps per tile */
#define NT (LL/ST)      /* 196 tiles */

typedef unsigned long long u64;

// ---------------- device scratch (static, no runtime alloc) ----------------
__device__ float2 g_dz[2*Bb*Kk*LL*Dd + PF*Dd];   // (softplus(delta), delta*u), traversal order
__device__ float2 g_BC[2*Bb*Kk*LL*16 + PF*16];   // per (row,no): {B0,B1},{C0,C1}, traversal order
__device__ float  g_yk[2*Bb*Kk*LL*Dd];           // per-direction scan outputs (traversal idx)
__device__ float  g_xT[2*Bb*LL*Dd];              // x transposed to [pos][d] (canonical)

__device__ __forceinline__ float ex2(float x) {
    float r; asm("ex2.approx.ftz.f32 %0, %1;" : "=f"(r) : "f"(x)); return r;
}
__device__ __forceinline__ float lg2(float x) {
    float r; asm("lg2.approx.ftz.f32 %0, %1;" : "=f"(r) : "f"(x)); return r;
}
__device__ __forceinline__ u64 ffma2(u64 a, u64 b, u64 c) {
    u64 r; asm("fma.rn.f32x2 %0, %1, %2, %3;" : "=l"(r) : "l"(a), "l"(b), "l"(c)); return r;
}
__device__ __forceinline__ float hadd2(u64 v) {
    float lo, hi; asm("mov.b64 {%0, %1}, %2;" : "=f"(lo), "=f"(hi) : "l"(v)); return lo + hi;
}
#define LOG2E 1.44269504088896340736f
#define LN2   0.69314718055994530942f

__device__ __forceinline__ int tau_of(int k, int pos) {
    int t1 = (pos % Ww) * Hh + pos / Ww;
    switch (k) {
        case 0: return pos;
        case 1: return t1;
        case 2: return LL - 1 - pos;
        default: return LL - 1 - t1;
    }
}

// ---------------- kernel 1: projections + precompute (unchanged from R6) ----------------
__global__ void __launch_bounds__(256, 2)
prep_kernel(const float* __restrict__ x1, const float* __restrict__ x2,
            const float* __restrict__ pw1, const float* __restrict__ pw2,
            const float* __restrict__ dtw1, const float* __restrict__ dtw2,
            const float* __restrict__ dtb1, const float* __restrict__ dtb2)
{
    extern __shared__ float sm[];
    float* xs   = sm;                    // [TP][XSTR]
    float* Ws   = xs + TP*XSTR;          // [48][192]
    float* dtws = Ws + CHP*Dd;           // [192][12]
    float* bsm  = dtws + Dd*12;          // [192]
    float* dblS = bsm + Dd;              // [48][DSTR]

    const int t    = threadIdx.x;
    const int pos0 = blockIdx.x * TP;
    const int k    = blockIdx.y;
    const int sbz  = blockIdx.z;
    const int s    = sbz >> 1, b = sbz & 1;
    const float* x   = s ? x2   : x1;
    const float* pw  = s ? pw2  : pw1;
    const float* dtw = s ? dtw2 : dtw1;
    const float* dtb = s ? dtb2 : dtb1;
    const int sb  = s*2 + b;
    const int sbo = (s^1)*2 + b;

    for (int e = t; e < Dd*TP; e += 256) {
        int d = e / TP, p = e % TP;
        xs[p*XSTR + d] = x[(b*Dd + d)*LL + pos0 + p];
    }
    for (int e = t; e < CHP*Dd; e += 256) Ws[e] = (e < CH*Dd) ? pw[k*CH*Dd + e] : 0.f;
    for (int e = t; e < Dd*Rr; e += 256) dtws[e] = dtw[k*Dd*Rr + e];
    if (t < Dd) bsm[t] = dtb[k*Dd + t];
    __syncthreads();

    if (k == 0) {
        for (int e = t; e < TP*Dd; e += 256) {
            int p = e / Dd, d = e - p*Dd;
            g_xT[(size_t)(sb*LL + pos0 + p)*Dd + d] = xs[p*XSTR + d];
        }
    }

    const int pg = t & 15;
    const int cb = t >> 4;

    {
        u64 acc2[4][3];
        #pragma unroll
        for (int i = 0; i < 4; i++)
            #pragma unroll
            for (int j = 0; j < 3; j++) acc2[i][j] = 0ull;

        #pragma unroll 2
        for (int d4 = 0; d4 < Dd; d4 += 4) {
            ulonglong2 w0 = *(const ulonglong2*)&Ws[ cb      *Dd + d4];
            ulonglong2 w1 = *(const ulonglong2*)&Ws[(cb+16) *Dd + d4];
            ulonglong2 w2 = *(const ulonglong2*)&Ws[(cb+32) *Dd + d4];
            #pragma unroll
            for (int i = 0; i < 4; i++) {
                ulonglong2 xv = *(const ulonglong2*)&xs[(pg + 16*i)*XSTR + d4];
                acc2[i][0] = ffma2(xv.x, w0.x, acc2[i][0]);
                acc2[i][0] = ffma2(xv.y, w0.y, acc2[i][0]);
                acc2[i][1] = ffma2(xv.x, w1.x, acc2[i][1]);
                acc2[i][1] = ffma2(xv.y, w1.y, acc2[i][1]);
                acc2[i][2] = ffma2(xv.x, w2.x, acc2[i][2]);
                acc2[i][2] = ffma2(xv.y, w2.y, acc2[i][2]);
            }
        }
        #pragma unroll
        for (int i = 0; i < 4; i++) {
            dblS[ cb     *DSTR + pg + 16*i] = hadd2(acc2[i][0]);
            dblS[(cb+16) *DSTR + pg + 16*i] = hadd2(acc2[i][1]);
            dblS[(cb+32) *DSTR + pg + 16*i] = hadd2(acc2[i][2]);
        }
    }
    __syncthreads();

    for (int e = t; e < TP*8; e += 256) {
        int p = e >> 3, no = e & 7;
        int tauv = tau_of(k, pos0 + p);
        float2 bv = make_float2(dblS[(12+no)*DSTR+p], dblS[(20+no)*DSTR+p]);
        float2 cv = make_float2(dblS[(28+no)*DSTR+p], dblS[(36+no)*DSTR+p]);
        g_BC[((size_t)(sb *Kk + k)*LL + tauv)*16 + no*2    ] = bv;
        g_BC[((size_t)(sbo*Kk + k)*LL + tauv)*16 + no*2 + 1] = cv;
    }

    for (int e = t; e < TP*Dd; e += 256) {
        int p = e / Dd, d = e - p*Dd;
        const float4* dw = (const float4*)&dtws[d*12];
        float4 wa = dw[0], wb = dw[1], wc = dw[2];
        float a = bsm[d];
        a = fmaf(wa.x, dblS[0*DSTR+p],  a); a = fmaf(wa.y, dblS[1*DSTR+p],  a);
        a = fmaf(wa.z, dblS[2*DSTR+p],  a); a = fmaf(wa.w, dblS[3*DSTR+p],  a);
        a = fmaf(wb.x, dblS[4*DSTR+p],  a); a = fmaf(wb.y, dblS[5*DSTR+p],  a);
        a = fmaf(wb.z, dblS[6*DSTR+p],  a); a = fmaf(wb.w, dblS[7*DSTR+p],  a);
        a = fmaf(wc.x, dblS[8*DSTR+p],  a); a = fmaf(wc.y, dblS[9*DSTR+p],  a);
        a = fmaf(wc.z, dblS[10*DSTR+p], a); a = fmaf(wc.w, dblS[11*DSTR+p], a);
        float em = ex2(-fabsf(a) * LOG2E);
        float sp = fmaxf(a, 0.f) + lg2(1.f + em) * LN2;
        float z  = sp * xs[p*XSTR + d];
        int tauv = tau_of(k, pos0 + p);
        g_dz[((size_t)(sb*Kk + k)*LL + tauv)*Dd + d] = make_float2(sp, z);
    }
}

// ---------------- kernel 2: selective scan ----------------
// grid (12, K, SB), 128 threads, warps independent. Butterfly reduce-scatter:
// 14 SHFL per 16-step tile (vs 48), stores distributed over all 32 lanes.
__global__ void __launch_bounds__(128) scan_kernel(const float* __restrict__ A1,
                                                   const float* __restrict__ A2)
{
    __shared__ float2 s_dz[4][4][ST*4];   // [warp][stage]  8 KB
    __shared__ float4 s_bc[4][4][ST*8];   // [warp][stage] 32 KB

    const int tid  = threadIdx.x;
    const int w    = tid >> 5;
    const int lane = tid & 31;
    const int dl = lane >> 3, no = lane & 7;
    const int k  = blockIdx.y;
    const int sb = blockIdx.z;
    const int s  = sb >> 1;
    const int d0 = blockIdx.x*16 + w*4;
    const int d  = d0 + dl;

    const float* Alog = s ? A2 : A1;
    const float a0 = -__expf(Alog[(k*Dd + d)*Nn + no    ]) * LOG2E;
    const float a1 = -__expf(Alog[(k*Dd + d)*Nn + no + 8]) * LOG2E;

    const int row0 = (sb*Kk + k)*LL;
    const size_t dz_row_f4 = Dd/2;
    const float4* dz_src = (const float4*)g_dz + ((size_t)row0 + (lane>>1))*dz_row_f4
                         + (d0>>1) + (lane&1);
    const float4* bc_src = (const float4*)g_BC + (size_t)row0*8 + lane;
    float* yp = g_yk + (size_t)row0*Dd + d;

    // this lane's output steps after the reduce-scatter (s0, s0+1)
    const int s0 = ((no & 1) << 3) | ((no & 2) << 1) | ((no & 4) >> 1);

    #define LOAD_TILE(slot, tile) do {                                                   \
        unsigned za = (unsigned)__cvta_generic_to_shared(&s_dz[w][slot][2*lane]);        \
        asm volatile("cp.async.cg.shared.global [%0], [%1], 16;" ::                      \
                     "r"(za), "l"(dz_src + (size_t)(tile)*ST*dz_row_f4));                \
        _Pragma("unroll")                                                                \
        for (int q = 0; q < 4; q++) {                                                    \
            unsigned ba = (unsigned)__cvta_generic_to_shared(&s_bc[w][slot][q*32+lane]); \
            asm volatile("cp.async.cg.shared.global [%0], [%1], 16;" ::                  \
                         "r"(ba), "l"(bc_src + (size_t)(tile)*ST*8 + q*32));             \
        }                                                                                \
        asm volatile("cp.async.commit_group;");                                          \
    } while (0)

    LOAD_TILE(0, 0);
    LOAD_TILE(1, 1);
    LOAD_TILE(2, 2);

    float h0 = 0.f, h1 = 0.f;
    for (int it = 0; it < NT; it++) {
        const int slot = it & 3;
        const int tt = it * ST;
        asm volatile("cp.async.wait_group 2;");
        __syncwarp();
        LOAD_TILE((it + 3) & 3, it + 3);    // pad region covers the tail tiles

        float yy[16];
        #pragma unroll
        for (int hb = 0; hb < 2; hb++) {
            float2 dzr[8]; float4 bcr[8];
            #pragma unroll
            for (int j = 0; j < 8; j++) {
                dzr[j] = s_dz[w][slot][(hb*8 + j)*4 + dl];
                bcr[j] = s_bc[w][slot][(hb*8 + j)*8 + no];
            }
            float e0[8], e1[8];
            #pragma unroll
            for (int j = 0; j < 8; j++) {
                e0[j] = ex2(dzr[j].x * a0);
                e1[j] = ex2(dzr[j].x * a1);
            }
            #pragma unroll
            for (int j = 0; j < 8; j++) {
                h0 = fmaf(e0[j], h0, dzr[j].y * bcr[j].x);
                h1 = fmaf(e1[j], h1, dzr[j].y * bcr[j].y);
                yy[hb*8 + j] = fmaf(h1, bcr[j].w, h0 * bcr[j].z);
            }
        }

        // butterfly reduce-scatter over the 8 n-lanes of each d-group:
        // round 1 (xor 1): halves [0..7] vs [8..15]
        #pragma unroll
        for (int j = 0; j < 8; j++) {
            float send = (no & 1) ? yy[j] : yy[8 + j];
            float recv = __shfl_xor_sync(0xffffffffu, send, 1);
            yy[j] = ((no & 1) ? yy[8 + j] : yy[j]) + recv;
        }
        // round 2 (xor 2): halves [0..3] vs [4..7]
        #pragma unroll
        for (int j = 0; j < 4; j++) {
            float send = (no & 2) ? yy[j] : yy[4 + j];
            float recv = __shfl_xor_sync(0xffffffffu, send, 2);
            yy[j] = ((no & 2) ? yy[4 + j] : yy[j]) + recv;
        }
        // round 3 (xor 4): halves [0..1] vs [2..3]
        #pragma unroll
        for (int j = 0; j < 2; j++) {
            float send = (no & 4) ? yy[j] : yy[2 + j];
            float recv = __shfl_xor_sync(0xffffffffu, send, 4);
            yy[j] = ((no & 4) ? yy[2 + j] : yy[j]) + recv;
        }
        // lane holds full sums for steps s0 and s0+1; all 32 lanes store
        yp[(tt + s0    )*Dd] = yy[0];
        yp[(tt + s0 + 1)*Dd] = yy[1];
    }
    asm volatile("cp.async.wait_group 0;");
    #undef LOAD_TILE
}

// ---------------- kernel 3: merge (sum k) + D*u + LayerNorm ----------------
__global__ void merge_ln_kernel(const float* __restrict__ D1s, const float* __restrict__ D2s,
                                const float* __restrict__ lnw, const float* __restrict__ lnb,
                                float* __restrict__ out)
{
    __shared__ float red[6];
    const int rid = blockIdx.x;
    const int sb = rid / LL, pos = rid % LL;
    const int s = sb >> 1;
    const int d = threadIdx.x;
    const float* Ds = s ? D2s : D1s;

    const int t1 = (pos % Ww) * Hh + pos / Ww;
    const int base = sb*Kk*LL;
    float v = g_yk[(size_t)(base          + pos       )*Dd + d]
            + g_yk[(size_t)(base + 1*LL   + t1        )*Dd + d]
            + g_yk[(size_t)(base + 2*LL   + (LL-1-pos))*Dd + d]
            + g_yk[(size_t)(base + 3*LL   + (LL-1-t1) )*Dd + d];
    const float Dsum = Ds[d] + Ds[Dd + d] + Ds[2*Dd + d] + Ds[3*Dd + d];
    v = fmaf(Dsum, g_xT[(size_t)(sb*LL + pos)*Dd + d], v);

    float tsum = v;
    #pragma unroll
    for (int o = 16; o; o >>= 1) tsum += __shfl_xor_sync(0xffffffffu, tsum, o);
    if ((d & 31) == 0) red[d >> 5] = tsum;
    __syncthreads();
    const float mu = (red[0]+red[1]+red[2]+red[3]+red[4]+red[5]) * (1.f/192.f);
    const float dv = v - mu;
    __syncthreads();
    float q = dv*dv;
    #pragma unroll
    for (int o = 16; o; o >>= 1) q += __shfl_xor_sync(0xffffffffu, q, o);
    if ((d & 31) == 0) red[d >> 5] = q;
    __syncthreads();
    const float var = (red[0]+red[1]+red[2]+red[3]+red[4]+red[5]) * (1.f/192.f);

    out[rid*Dd + d] = dv * rsqrtf(var + 1e-5f) * lnw[d] + lnb[d];
}

// ---------------- launch ----------------
extern "C" void kernel_launch(void* const* d_in, const int* in_sizes, int n_in,
                              void* d_out, int out_size)
{
    const float* x1   = (const float*)d_in[0];
    const float* x2   = (const float*)d_in[1];
    const float* pw1  = (const float*)d_in[2];
    const float* pw2  = (const float*)d_in[3];
    const float* dtw1 = (const float*)d_in[4];
    const float* dtw2 = (const float*)d_in[5];
    const float* dtb1 = (const float*)d_in[6];
    const float* dtb2 = (const float*)d_in[7];
    const float* A1   = (const float*)d_in[8];
    const float* A2   = (const float*)d_in[9];
    const float* D1s  = (const float*)d_in[10];
    const float* D2s  = (const float*)d_in[11];
    const float* lnw  = (const float*)d_in[12];
    const float* lnb  = (const float*)d_in[13];
    float* out = (float*)d_out;

    const int smem = (TP*XSTR + CHP*Dd + Dd*12 + Dd + CHP*DSTR) * (int)sizeof(float); // 109,696 B
    cudaFuncSetAttribute(prep_kernel, cudaFuncAttributeMaxDynamicSharedMemorySize, smem);

    prep_kernel<<<dim3(LL/TP, Kk, 4), 256, smem>>>(x1, x2, pw1, pw2, dtw1, dtw2, dtb1, dtb2);
    scan_kernel<<<dim3(Dd/16, Kk, 2*Bb), 128>>>(A1, A2);
    merge_ln_kernel<<<2*Bb*LL, Dd>>>(D1s, D2s, lnw, lnb, out);
}